// round 16
// baseline (speedup 1.0000x reference)
#include <cuda_runtime.h>
#include <cuda_fp16.h>
#include <cstdint>

#define OBSD 128
#define ACTD 32
#define HIDD 256
#define NP   64
#define NB   4096
#define MT   64
#define EPSV 1e-5f

// ---------------- SMEM layout (bytes) ----------------
#define AFRAG_HI 0          // 4 mtiles x 16 ktiles x 32 lanes x 16B = 32KB (fp16 hi only)
#define PAR0_OFF 32768      // 768 floats
#define PAR1_OFF 35840      // 768 floats
#define RED1_OFF 38912      // 4*64 floats (col-group partials)
#define RED2_OFF 40960      // 4*64 floats
#define DSMEM_BYTES 43008

// ---------------- weight fragment image ----------------
// image element (uint4): {hi_r0, hi_r1, lo_r0, lo_r1}; single-term path reads
// only the first 8 bytes (uint2 view).
#define L1_BYTES ((size_t)OBSD*HIDD*4)
#define L2_BYTES ((size_t)HIDD*HIDD*4)
#define L4_BYTES ((size_t)HIDD*ACTD*4)
#define OFF_L1 0ull
#define OFF_L2 (OFF_L1 + 64ull*L1_BYTES)
#define OFF_L3 (OFF_L2 + 64ull*L2_BYTES)
#define OFF_L4 (OFF_L3 + 64ull*L2_BYTES)
#define WIMG_TOTAL (OFF_L4 + 64ull*L4_BYTES)

__device__ __align__(128) unsigned char g_wimg[WIMG_TOTAL];

// ---------------- helpers ----------------
__device__ __forceinline__ void mma16816(float* c, const uint4& a, uint32_t b0, uint32_t b1) {
    asm volatile(
        "mma.sync.aligned.m16n8k16.row.col.f32.f16.f16.f32 "
        "{%0,%1,%2,%3}, {%4,%5,%6,%7}, {%8,%9}, {%0,%1,%2,%3};"
        : "+f"(c[0]), "+f"(c[1]), "+f"(c[2]), "+f"(c[3])
        : "r"(a.x), "r"(a.y), "r"(a.z), "r"(a.w), "r"(b0), "r"(b1));
}

__device__ __forceinline__ uint32_t pack_f16(float y0, float y1) {
    uint32_t r;
    asm("cvt.rn.f16x2.f32 %0, %2, %1;" : "=r"(r) : "f"(y0), "f"(y1));
    return r;
}

__device__ __forceinline__ void split_pack_f16(float y0, float y1, uint32_t& hp, uint32_t& lp) {
    hp = pack_f16(y0, y1);
    float f0 = __half2float(__ushort_as_half((unsigned short)(hp & 0xffffu)));
    float f1 = __half2float(__ushort_as_half((unsigned short)(hp >> 16)));
    lp = pack_f16(y0 - f0, y1 - f1);
}

// ---- packed f32x2 (sm_10x) ----
__device__ __forceinline__ uint64_t pk2(float lo, float hi) {
    uint64_t r; asm("mov.b64 %0, {%1, %2};" : "=l"(r) : "f"(lo), "f"(hi)); return r;
}
__device__ __forceinline__ void upk2(uint64_t v, float& lo, float& hi) {
    asm("mov.b64 {%0, %1}, %2;" : "=f"(lo), "=f"(hi) : "l"(v));
}
__device__ __forceinline__ uint64_t add2(uint64_t a, uint64_t b) {
    uint64_t r; asm("add.rn.f32x2 %0, %1, %2;" : "=l"(r) : "l"(a), "l"(b)); return r;
}
__device__ __forceinline__ uint64_t fma2(uint64_t a, uint64_t b, uint64_t c) {
    uint64_t r; asm("fma.rn.f32x2 %0, %1, %2, %3;" : "=l"(r) : "l"(a), "l"(b), "l"(c)); return r;
}

// packed ELU on f16x2: exact for y>=0; f16-approx exp for y<0
__device__ __forceinline__ uint32_t elu_h2(uint32_t h) {
    __half2 y = *reinterpret_cast<__half2*>(&h);
    const __half2 z = __float2half2_rn(0.f);
    const __half2 l2e = __float2half2_rn(1.4426950408889634f);
    const __half2 one = __float2half2_rn(1.f);
    __half2 pos = __hmax2(y, z);
    __half2 neg = __hmin2(y, z);
    __half2 e = h2exp2(__hmul2(neg, l2e));
    __half2 res = __hadd2(pos, __hsub2(e, one));
    return *reinterpret_cast<uint32_t*>(&res);
}

// ---------------- weight preprocess (merged, validated) ----------------
template<int N, int K>
__device__ __forceinline__ void prep_dev(const float* __restrict__ W, size_t off, float* tile)
{
    const int p = blockIdx.x, kt = blockIdx.y;
    if (kt >= K / 16) return;
    const int tid = threadIdx.x;
    const float4* src = reinterpret_cast<const float4*>(W + ((size_t)p * K + (size_t)kt * 16) * N);
    constexpr int NL4 = 16 * N / 4;
    for (int i = tid; i < NL4; i += 256)
        reinterpret_cast<float4*>(tile)[i] = src[i];
    __syncthreads();
    constexpr int NT = N / 8;
    uint4* dst = reinterpret_cast<uint4*>(g_wimg + off + (size_t)p * ((size_t)K * N * 4));
    for (int u = tid; u < NT * 32; u += 256) {
        int nt = u >> 5, lane = u & 31;
        int n = nt * 8 + (lane >> 2), q = (lane & 3) * 2;
        uint32_t hp[2], lp[2];
#pragma unroll
        for (int r = 0; r < 2; r++) {
            float w0 = tile[(q + 8 * r) * N + n];
            float w1 = tile[(q + 8 * r + 1) * N + n];
            split_pack_f16(w0, w1, hp[r], lp[r]);
        }
        uint4 v; v.x = hp[0]; v.y = hp[1]; v.z = lp[0]; v.w = lp[1];
        dst[((size_t)kt * NT + nt) * 32 + lane] = v;
    }
}

__global__ void prep_all_kernel(const float* __restrict__ W1, const float* __restrict__ W2,
                                const float* __restrict__ W3, const float* __restrict__ W4)
{
    __shared__ float tile[16 * HIDD];
    switch (blockIdx.z) {
        case 0: prep_dev<HIDD, OBSD>(W1, OFF_L1, tile); break;
        case 1: prep_dev<HIDD, HIDD>(W2, OFF_L2, tile); break;
        case 2: prep_dev<HIDD, HIDD>(W3, OFF_L3, tile); break;
        default: prep_dev<ACTD, HIDD>(W4, OFF_L4, tile); break;
    }
}

// ---------------- fused main kernel ----------------
// A-fragment smem layout: idx(m,k) -> uint32 slot (m in [0,64)), fp16 hi only
//   mtile=m/16, ktile=k/16, a_lane=(m%8)*4+((k%8)/2), r=2*((k%16)>=8)+((m%16)>=8)
//   idx = ((mtile*16 + ktile)*32 + a_lane)*4 + r
// 8 warps = 2 m-halves x 4 col-groups: warp (mh, cg) computes rows [mh*32, +32)
// x cols [cg*64, +64) -> acc[2 mtiles][8 nt][4]. A LDS per kt: 2 (was 4).
// Single-term MMA: D = Ah * W_hi (pure fp16, fp32 accum).

template<int K, bool ACT, int NEXTN>
__device__ __forceinline__ void hidden_layer(
    unsigned char* smem, const uint4* __restrict__ bfr,
    const float* __restrict__ nb, const float* __restrict__ ng, const float* __restrict__ nbe,
    const float* parC, float* parN, int tid)
{
    const int lane = tid & 31;
    const int wid  = tid >> 5;
    const int cg   = wid & 3;        // col group: cols [cg*64, +64)
    const int mh   = wid >> 2;       // m half: rows [mh*32, +32)
    uint32_t* ah = reinterpret_cast<uint32_t*>(smem + AFRAG_HI);
    float* red1 = reinterpret_cast<float*>(smem + RED1_OFF);
    float* red2 = reinterpret_cast<float*>(smem + RED2_OFF);
    const uint4* ah4 = reinterpret_cast<const uint4*>(ah);

    float acc[2][8][4];
#pragma unroll
    for (int q = 0; q < 2; q++)
#pragma unroll
        for (int nt = 0; nt < 8; nt++)
#pragma unroll
            for (int r = 0; r < 4; r++) acc[q][nt][r] = 0.f;

    const uint4* bwarp = bfr + (size_t)cg * 256 + lane;   // + kt*1024 + nt*32
    constexpr int KTN = K / 16;

    uint2 B[8];
#pragma unroll
    for (int nt = 0; nt < 8; nt++)
        B[nt] = __ldg(reinterpret_cast<const uint2*>(bwarp + nt * 32));

#pragma unroll 1
    for (int kt = 0; kt < KTN; kt++) {
        uint2 Bn[8];
        if (kt + 1 < KTN) {
#pragma unroll
            for (int nt = 0; nt < 8; nt++)
                Bn[nt] = __ldg(reinterpret_cast<const uint2*>(bwarp + (size_t)(kt + 1) * 1024 + nt * 32));
        }
#pragma unroll
        for (int q = 0; q < 2; q++) {
            uint4 Ah = ah4[((mh * 2 + q) * 16 + kt) * 32 + lane];
#pragma unroll
            for (int nt = 0; nt < 8; nt++)
                mma16816(acc[q][nt], Ah, B[nt].x, B[nt].y);   // A * W_hi
        }
#pragma unroll
        for (int nt = 0; nt < 8; nt++) B[nt] = Bn[nt];
    }

    // stage NEXT layer's params (overlaps epilogue)
    for (int i = tid; i < 3 * NEXTN; i += 256)
        parN[i] = (i < NEXTN) ? nb[i] : (i < 2 * NEXTN ? ng[i - NEXTN] : nbe[i - 2 * NEXTN]);

    // P1: bias + per-row partial sums, packed f32x2
    const int nbase = cg * 64 + (lane & 3) * 2;
    uint64_t bb2[8];
#pragma unroll
    for (int nt = 0; nt < 8; nt++) {
        float2 b2 = *reinterpret_cast<const float2*>(parC + nbase + nt * 8);
        bb2[nt] = pk2(b2.x, b2.y);
    }

#pragma unroll
    for (int q = 0; q < 2; q++) {
        uint64_t s1a2 = 0ull, s2a2 = 0ull, s1b2 = 0ull, s2b2 = 0ull;   // {0.f,0.f}
#pragma unroll
        for (int nt = 0; nt < 8; nt++) {
            uint64_t y01 = add2(pk2(acc[q][nt][0], acc[q][nt][1]), bb2[nt]);
            uint64_t y23 = add2(pk2(acc[q][nt][2], acc[q][nt][3]), bb2[nt]);
            upk2(y01, acc[q][nt][0], acc[q][nt][1]);
            upk2(y23, acc[q][nt][2], acc[q][nt][3]);
            s1a2 = add2(s1a2, y01); s2a2 = fma2(y01, y01, s2a2);
            s1b2 = add2(s1b2, y23); s2b2 = fma2(y23, y23, s2b2);
        }
        float u, v;
        upk2(s1a2, u, v); float s1a = u + v;
        upk2(s2a2, u, v); float s2a = u + v;
        upk2(s1b2, u, v); float s1b = u + v;
        upk2(s2b2, u, v); float s2b = u + v;
        s1a += __shfl_xor_sync(~0u, s1a, 1); s1a += __shfl_xor_sync(~0u, s1a, 2);
        s2a += __shfl_xor_sync(~0u, s2a, 1); s2a += __shfl_xor_sync(~0u, s2a, 2);
        s1b += __shfl_xor_sync(~0u, s1b, 1); s1b += __shfl_xor_sync(~0u, s1b, 2);
        s2b += __shfl_xor_sync(~0u, s2b, 1); s2b += __shfl_xor_sync(~0u, s2b, 2);
        if ((lane & 3) == 0) {
            int m0 = mh * 32 + q * 16 + (lane >> 2);
            red1[cg * 64 + m0]     = s1a; red2[cg * 64 + m0]     = s2a;
            red1[cg * 64 + m0 + 8] = s1b; red2[cg * 64 + m0 + 8] = s2b;
        }
    }
    __syncthreads();
    if (tid < 64) {
        float t1 = red1[tid] + red1[64 + tid] + red1[128 + tid] + red1[192 + tid];
        float t2 = red2[tid] + red2[64 + tid] + red2[128 + tid] + red2[192 + tid];
        float mean = t1 * (1.f / 256.f);
        float var  = fmaf(-mean, mean, t2 * (1.f / 256.f));
        float rstd = rsqrtf(var + EPSV);
        red1[tid] = mean; red2[tid] = rstd;
    }
    __syncthreads();

    // P3: packed-f32x2 normalize + packed-h2 activation + uint4 A-frag stores
    uint64_t gg2[8], ee2[8];
#pragma unroll
    for (int nt = 0; nt < 8; nt++) {
        float2 g2 = *reinterpret_cast<const float2*>(parC + 256 + nbase + nt * 8);
        float2 e2 = *reinterpret_cast<const float2*>(parC + 512 + nbase + nt * 8);
        gg2[nt] = pk2(g2.x, g2.y);
        ee2[nt] = pk2(e2.x, e2.y);
    }
    const int aln = ((lane >> 2) << 2) + (lane & 3);
#pragma unroll
    for (int q = 0; q < 2; q++) {
        int mA = mh * 32 + q * 16 + (lane >> 2);
        float meanA = red1[mA],     rstdA = red2[mA];
        float meanB = red1[mA + 8], rstdB = red2[mA + 8];
        uint64_t rA2 = pk2(rstdA, rstdA);
        uint64_t rB2 = pk2(rstdB, rstdB);
        float mrA = -meanA * rstdA, mrB = -meanB * rstdB;
        uint64_t mA2 = pk2(mrA, mrA);
        uint64_t mB2 = pk2(mrB, mrB);
#pragma unroll
        for (int jp = 0; jp < 4; jp++) {     // ktile pair: nt = 2jp, 2jp+1
            uint32_t hv[4];
#pragma unroll
            for (int h = 0; h < 2; h++) {
                int nt = jp * 2 + h;
                uint64_t t01 = fma2(pk2(acc[q][nt][0], acc[q][nt][1]), rA2, mA2);
                uint64_t t23 = fma2(pk2(acc[q][nt][2], acc[q][nt][3]), rB2, mB2);
                uint64_t r01 = fma2(t01, gg2[nt], ee2[nt]);
                uint64_t r23 = fma2(t23, gg2[nt], ee2[nt]);
                float f0, f1, f2, f3;
                upk2(r01, f0, f1);
                upk2(r23, f2, f3);
                uint32_t hp0 = pack_f16(f0, f1);
                uint32_t hp1 = pack_f16(f2, f3);
                if (ACT) { hp0 = elu_h2(hp0); hp1 = elu_h2(hp1); }
                hv[h * 2]     = hp0;     // rows mA
                hv[h * 2 + 1] = hp1;     // rows mA+8
            }
            int idxb = (((mh * 2 + q) * 16 + cg * 4 + jp) * 32 + aln) * 4;
            *reinterpret_cast<uint4*>(ah + idxb) = make_uint4(hv[0], hv[1], hv[2], hv[3]);
        }
    }
    __syncthreads();
}

// final layer: K=256, N=32, 64 rows. Split-K across warp halves. (no ELU)
__device__ __forceinline__ void final_layer(
    unsigned char* smem, const uint4* __restrict__ bfr,
    const float* parC, float* __restrict__ out, int r0, int p, int tid)
{
    const int lane = tid & 31, wid = tid >> 5;
    const int m = wid & 3, kh = wid >> 2;
    const uint4* ah4 = reinterpret_cast<const uint4*>(smem + AFRAG_HI);
    float* scr = reinterpret_cast<float*>(smem);       // reused after barrier

    float acc[4][4];
#pragma unroll
    for (int nt = 0; nt < 4; nt++)
#pragma unroll
        for (int r = 0; r < 4; r++) acc[nt][r] = 0.f;

#pragma unroll 1
    for (int k = 0; k < 8; k++) {
        const int kt = kh * 8 + k;
        uint2 B[4];
#pragma unroll
        for (int nt = 0; nt < 4; nt++)
            B[nt] = __ldg(reinterpret_cast<const uint2*>(&bfr[((size_t)kt * 4 + nt) * 32 + lane]));
        uint4 Ah = ah4[(m * 16 + kt) * 32 + lane];
#pragma unroll
        for (int nt = 0; nt < 4; nt++)
            mma16816(acc[nt], Ah, B[nt].x, B[nt].y);
    }
    __syncthreads();     // all A-frag reads done; smem reusable
    if (kh == 1) {
        float4* s4 = reinterpret_cast<float4*>(scr) + (m * 32 + lane) * 4;
#pragma unroll
        for (int nt = 0; nt < 4; nt++)
            s4[nt] = make_float4(acc[nt][0], acc[nt][1], acc[nt][2], acc[nt][3]);
    }
    __syncthreads();
    if (kh == 1) return;

    const float4* s4 = reinterpret_cast<const float4*>(scr) + (m * 32 + lane) * 4;
#pragma unroll
    for (int nt = 0; nt < 4; nt++) {
        float4 v = s4[nt];
        acc[nt][0] += v.x; acc[nt][1] += v.y; acc[nt][2] += v.z; acc[nt][3] += v.w;
    }

    // bias + stats (warp-local: warp covers all 32 cols)
    const int nbase = (lane & 3) * 2;
    float s1a = 0.f, s2a = 0.f, s1b = 0.f, s2b = 0.f;
#pragma unroll
    for (int nt = 0; nt < 4; nt++) {
        float2 b2 = *reinterpret_cast<const float2*>(parC + nbase + nt * 8);
        float y0 = acc[nt][0] + b2.x, y1 = acc[nt][1] + b2.y;
        float y2 = acc[nt][2] + b2.x, y3 = acc[nt][3] + b2.y;
        acc[nt][0] = y0; acc[nt][1] = y1; acc[nt][2] = y2; acc[nt][3] = y3;
        s1a += y0 + y1; s2a = fmaf(y0, y0, fmaf(y1, y1, s2a));
        s1b += y2 + y3; s2b = fmaf(y2, y2, fmaf(y3, y3, s2b));
    }
    s1a += __shfl_xor_sync(~0u, s1a, 1); s1a += __shfl_xor_sync(~0u, s1a, 2);
    s2a += __shfl_xor_sync(~0u, s2a, 1); s2a += __shfl_xor_sync(~0u, s2a, 2);
    s1b += __shfl_xor_sync(~0u, s1b, 1); s1b += __shfl_xor_sync(~0u, s1b, 2);
    s2b += __shfl_xor_sync(~0u, s2b, 1); s2b += __shfl_xor_sync(~0u, s2b, 2);
    const float meanA = s1a * (1.f / 32.f);
    const float rstdA = rsqrtf(fmaf(-meanA, meanA, s2a * (1.f / 32.f)) + EPSV);
    const float meanB = s1b * (1.f / 32.f);
    const float rstdB = rsqrtf(fmaf(-meanB, meanB, s2b * (1.f / 32.f)) + EPSV);

    const int mA = m * 16 + (lane >> 2);
#pragma unroll
    for (int nt = 0; nt < 4; nt++) {
        int n0 = nbase + nt * 8;
        float2 g2 = *reinterpret_cast<const float2*>(parC + 32 + n0);
        float2 e2 = *reinterpret_cast<const float2*>(parC + 64 + n0);
        float2 o;
        o.x = fmaf((acc[nt][0] - meanA) * rstdA, g2.x, e2.x);
        o.y = fmaf((acc[nt][1] - meanA) * rstdA, g2.y, e2.y);
        *reinterpret_cast<float2*>(out + (size_t)(r0 + mA) * (NP * ACTD) + p * ACTD + n0) = o;
        o.x = fmaf((acc[nt][2] - meanB) * rstdB, g2.x, e2.x);
        o.y = fmaf((acc[nt][3] - meanB) * rstdB, g2.y, e2.y);
        *reinterpret_cast<float2*>(out + (size_t)(r0 + mA + 8) * (NP * ACTD) + p * ACTD + n0) = o;
    }
}

__global__ __launch_bounds__(256, 2)
void mlp_fused_kernel(
    const float* __restrict__ obs,
    const float* __restrict__ b1, const float* __restrict__ g1, const float* __restrict__ be1,
    const float* __restrict__ b2, const float* __restrict__ g2, const float* __restrict__ be2,
    const float* __restrict__ b3, const float* __restrict__ g3, const float* __restrict__ be3,
    const float* __restrict__ b4, const float* __restrict__ g4, const float* __restrict__ be4,
    float* __restrict__ out)
{
    extern __shared__ unsigned char smem[];
    const int tid = threadIdx.x;
    const int p   = blockIdx.y;
    const int r0  = blockIdx.x * MT;
    uint32_t* ah = reinterpret_cast<uint32_t*>(smem + AFRAG_HI);
    float* par0 = reinterpret_cast<float*>(smem + PAR0_OFF);
    float* par1 = reinterpret_cast<float*>(smem + PAR1_OFF);

    // stage observation tile as fp16 A-fragments + layer-1 params
    {
        const int m = tid >> 2, q4 = tid & 3;
        const float* orow = obs + (size_t)(r0 + m) * OBSD + q4 * 32;
#pragma unroll
        for (int j = 0; j < 16; j++) {
            float2 v = reinterpret_cast<const float2*>(orow)[j];
            int k = q4 * 32 + j * 2;
            int aln = ((m & 7) << 2) + ((k & 7) >> 1);
            int r = (((k & 15) >= 8) ? 2 : 0) + (((m & 15) >= 8) ? 1 : 0);
            int idx = (((m >> 4) * 16 + (k >> 4)) * 32 + aln) * 4 + r;
            ah[idx] = pack_f16(v.x, v.y);
        }
        const float* s1 = b1 + p * HIDD;
        const float* s2 = g1 + p * HIDD;
        const float* s3 = be1 + p * HIDD;
        for (int i = tid; i < 768; i += 256)
            par0[i] = (i < 256) ? s1[i] : (i < 512 ? s2[i - 256] : s3[i - 512]);
    }
    __syncthreads();

    hidden_layer<OBSD, true, HIDD>(smem,
        reinterpret_cast<const uint4*>(g_wimg + OFF_L1 + (size_t)p * L1_BYTES),
        b2 + p * HIDD, g2 + p * HIDD, be2 + p * HIDD, par0, par1, tid);
    hidden_layer<HIDD, true, HIDD>(smem,
        reinterpret_cast<const uint4*>(g_wimg + OFF_L2 + (size_t)p * L2_BYTES),
        b3 + p * HIDD, g3 + p * HIDD, be3 + p * HIDD, par1, par0, tid);
    hidden_layer<HIDD, true, ACTD>(smem,
        reinterpret_cast<const uint4*>(g_wimg + OFF_L3 + (size_t)p * L2_BYTES),
        b4 + p * ACTD, g4 + p * ACTD, be4 + p * ACTD, par0, par1, tid);
    final_layer(smem,
        reinterpret_cast<const uint4*>(g_wimg + OFF_L4 + (size_t)p * L4_BYTES),
        par1, out, r0, p, tid);
}

// ---------------- launch ----------------
extern "C" void kernel_launch(void* const* d_in, const int* in_sizes, int n_in,
                              void* d_out, int out_size)
{
    const float* obs = (const float*)d_in[0];
    const float* W1  = (const float*)d_in[1];
    const float* b1  = (const float*)d_in[2];
    const float* g1  = (const float*)d_in[3];
    const float* be1 = (const float*)d_in[4];
    const float* W2  = (const float*)d_in[5];
    const float* b2  = (const float*)d_in[6];
    const float* g2  = (const float*)d_in[7];
    const float* be2 = (const float*)d_in[8];
    const float* W3  = (const float*)d_in[9];
    const float* b3  = (const float*)d_in[10];
    const float* g3  = (const float*)d_in[11];
    const float* be3 = (const float*)d_in[12];
    const float* W4  = (const float*)d_in[13];
    const float* b4  = (const float*)d_in[14];
    const float* g4  = (const float*)d_in[15];
    const float* be4 = (const float*)d_in[16];
    float* out = (float*)d_out;

    prep_all_kernel<<<dim3(NP, HIDD / 16, 4), 256>>>(W1, W2, W3, W4);

    cudaFuncSetAttribute(mlp_fused_kernel,
                         cudaFuncAttributeMaxDynamicSharedMemorySize, DSMEM_BYTES);
    dim3 grid(NB / MT, NP);
    mlp_fused_kernel<<<grid, 256, DSMEM_BYTES>>>(
        obs, b1, g1, be1, b2, g2, be2, b3, g3, be3, b4, g4, be4, out);
}

// round 17
// speedup vs baseline: 1.2417x; 1.2417x over previous
#include <cuda_runtime.h>
#include <cuda_fp16.h>
#include <cstdint>

#define OBSD 128
#define ACTD 32
#define HIDD 256
#define NP   64
#define NB   4096
#define MT   64
#define EPSV 1e-5f

// ---------------- SMEM layout (bytes) ----------------
#define AFRAG_HI 0          // 4 mtiles x 16 ktiles x 32 lanes x 16B = 32KB (fp16 hi only)
#define PAR0_OFF 32768      // 768 floats
#define PAR1_OFF 35840      // 768 floats
#define RED1_OFF 38912      // 8*64 floats
#define RED2_OFF 40960      // 8*64 floats
#define DSMEM_BYTES 43008

// ---------------- weight fragment image ----------------
// image element (uint4): {hi_r0, hi_r1, lo_r0, lo_r1}; single-term path reads
// only the first 8 bytes (uint2 view).
#define L1_BYTES ((size_t)OBSD*HIDD*4)
#define L2_BYTES ((size_t)HIDD*HIDD*4)
#define L4_BYTES ((size_t)HIDD*ACTD*4)
#define OFF_L1 0ull
#define OFF_L2 (OFF_L1 + 64ull*L1_BYTES)
#define OFF_L3 (OFF_L2 + 64ull*L2_BYTES)
#define OFF_L4 (OFF_L3 + 64ull*L2_BYTES)
#define WIMG_TOTAL (OFF_L4 + 64ull*L4_BYTES)

__device__ __align__(128) unsigned char g_wimg[WIMG_TOTAL];

// obs A-frag image: 64 tiles x (4 mtiles x 8 kt x 32 lanes x 16B) = 64 x 16KB
__device__ __align__(128) unsigned char g_obsimg[64 * 16384];

// ---------------- helpers ----------------
__device__ __forceinline__ void mma16816(float* c, const uint4& a, uint32_t b0, uint32_t b1) {
    asm volatile(
        "mma.sync.aligned.m16n8k16.row.col.f32.f16.f16.f32 "
        "{%0,%1,%2,%3}, {%4,%5,%6,%7}, {%8,%9}, {%0,%1,%2,%3};"
        : "+f"(c[0]), "+f"(c[1]), "+f"(c[2]), "+f"(c[3])
        : "r"(a.x), "r"(a.y), "r"(a.z), "r"(a.w), "r"(b0), "r"(b1));
}

__device__ __forceinline__ uint32_t pack_f16(float y0, float y1) {
    uint32_t r;
    asm("cvt.rn.f16x2.f32 %0, %2, %1;" : "=r"(r) : "f"(y0), "f"(y1));
    return r;
}

__device__ __forceinline__ void split_pack_f16(float y0, float y1, uint32_t& hp, uint32_t& lp) {
    hp = pack_f16(y0, y1);
    float f0 = __half2float(__ushort_as_half((unsigned short)(hp & 0xffffu)));
    float f1 = __half2float(__ushort_as_half((unsigned short)(hp >> 16)));
    lp = pack_f16(y0 - f0, y1 - f1);
}

// ---- packed f32x2 (sm_10x) ----
__device__ __forceinline__ uint64_t pk2(float lo, float hi) {
    uint64_t r; asm("mov.b64 %0, {%1, %2};" : "=l"(r) : "f"(lo), "f"(hi)); return r;
}
__device__ __forceinline__ void upk2(uint64_t v, float& lo, float& hi) {
    asm("mov.b64 {%0, %1}, %2;" : "=f"(lo), "=f"(hi) : "l"(v));
}
__device__ __forceinline__ uint64_t add2(uint64_t a, uint64_t b) {
    uint64_t r; asm("add.rn.f32x2 %0, %1, %2;" : "=l"(r) : "l"(a), "l"(b)); return r;
}
__device__ __forceinline__ uint64_t fma2(uint64_t a, uint64_t b, uint64_t c) {
    uint64_t r; asm("fma.rn.f32x2 %0, %1, %2, %3;" : "=l"(r) : "l"(a), "l"(b), "l"(c)); return r;
}

// packed ELU on f16x2: exact for y>=0; f16-approx exp for y<0
__device__ __forceinline__ uint32_t elu_h2(uint32_t h) {
    __half2 y = *reinterpret_cast<__half2*>(&h);
    const __half2 z = __float2half2_rn(0.f);
    const __half2 l2e = __float2half2_rn(1.4426950408889634f);
    const __half2 one = __float2half2_rn(1.f);
    __half2 pos = __hmax2(y, z);
    __half2 neg = __hmin2(y, z);
    __half2 e = h2exp2(__hmul2(neg, l2e));
    __half2 res = __hadd2(pos, __hsub2(e, one));
    return *reinterpret_cast<uint32_t*>(&res);
}

// ---------------- weight + obs preprocess (merged, z = layer) ----------------
template<int N, int K>
__device__ __forceinline__ void prep_dev(const float* __restrict__ W, size_t off, float* tile)
{
    const int p = blockIdx.x, kt = blockIdx.y;
    if (kt >= K / 16) return;
    const int tid = threadIdx.x;
    const float4* src = reinterpret_cast<const float4*>(W + ((size_t)p * K + (size_t)kt * 16) * N);
    constexpr int NL4 = 16 * N / 4;
    for (int i = tid; i < NL4; i += 256)
        reinterpret_cast<float4*>(tile)[i] = src[i];
    __syncthreads();
    constexpr int NT = N / 8;
    uint4* dst = reinterpret_cast<uint4*>(g_wimg + off + (size_t)p * ((size_t)K * N * 4));
    for (int u = tid; u < NT * 32; u += 256) {
        int nt = u >> 5, lane = u & 31;
        int n = nt * 8 + (lane >> 2), q = (lane & 3) * 2;
        uint32_t hp[2], lp[2];
#pragma unroll
        for (int r = 0; r < 2; r++) {
            float w0 = tile[(q + 8 * r) * N + n];
            float w1 = tile[(q + 8 * r + 1) * N + n];
            split_pack_f16(w0, w1, hp[r], lp[r]);
        }
        uint4 v; v.x = hp[0]; v.y = hp[1]; v.z = lp[0]; v.w = lp[1];
        dst[((size_t)kt * NT + nt) * 32 + lane] = v;
    }
}

// obs -> fp16 A-fragment image, compact 8-kt layout (one 64-row tile per block)
__device__ __forceinline__ void prep_obs_dev(const float* __restrict__ obs)
{
    if (blockIdx.y != 0) return;
    const int t   = blockIdx.x;         // tile 0..63
    const int tid = threadIdx.x;
    const int m = tid >> 2, q4 = tid & 3;
    uint32_t* img = reinterpret_cast<uint32_t*>(g_obsimg) + (size_t)t * 4096;
    const float* orow = obs + (size_t)(t * 64 + m) * OBSD + q4 * 32;
#pragma unroll
    for (int j = 0; j < 16; j++) {
        float2 v = reinterpret_cast<const float2*>(orow)[j];
        int k = q4 * 32 + j * 2;
        int aln = ((m & 7) << 2) + ((k & 7) >> 1);
        int r = (((k & 15) >= 8) ? 2 : 0) + (((m & 15) >= 8) ? 1 : 0);
        int idx = (((m >> 4) * 8 + (k >> 4)) * 32 + aln) * 4 + r;
        img[idx] = pack_f16(v.x, v.y);
    }
}

__global__ void prep_all_kernel(const float* __restrict__ W1, const float* __restrict__ W2,
                                const float* __restrict__ W3, const float* __restrict__ W4,
                                const float* __restrict__ obs)
{
    __shared__ float tile[16 * HIDD];
    switch (blockIdx.z) {
        case 0: prep_dev<HIDD, OBSD>(W1, OFF_L1, tile); break;
        case 1: prep_dev<HIDD, HIDD>(W2, OFF_L2, tile); break;
        case 2: prep_dev<HIDD, HIDD>(W3, OFF_L3, tile); break;
        case 3: prep_dev<ACTD, HIDD>(W4, OFF_L4, tile); break;
        default: prep_obs_dev(obs); break;
    }
}

// ---------------- fused main kernel ----------------
// A-fragment smem layout: idx(m,k) -> uint32 slot (m in [0,64)), fp16 hi only
//   mtile=m/16, ktile=k/16, a_lane=(m%8)*4+((k%8)/2), r=2*((k%16)>=8)+((m%16)>=8)
//   idx = ((mtile*16 + ktile)*32 + a_lane)*4 + r
// 8 warps: warp wn owns cols [wn*32, wn*32+32), computes all 4 mtiles (64 rows).
// Single-term MMA: D = Ah * W_hi (pure fp16, fp32 accum). B prefetch depth 2.

template<int K, bool ACT, int NEXTN>
__device__ __forceinline__ void hidden_layer(
    unsigned char* smem, const uint4* __restrict__ bfr,
    const float* __restrict__ nb, const float* __restrict__ ng, const float* __restrict__ nbe,
    const float* parC, float* parN, int tid)
{
    const int lane = tid & 31;
    const int wn   = tid >> 5;
    uint32_t* ah = reinterpret_cast<uint32_t*>(smem + AFRAG_HI);
    float* red1 = reinterpret_cast<float*>(smem + RED1_OFF);
    float* red2 = reinterpret_cast<float*>(smem + RED2_OFF);
    const uint4* ah4 = reinterpret_cast<const uint4*>(ah);

    float acc[4][4][4];
#pragma unroll
    for (int q = 0; q < 4; q++)
#pragma unroll
        for (int nt = 0; nt < 4; nt++)
#pragma unroll
            for (int r = 0; r < 4; r++) acc[q][nt][r] = 0.f;

    const uint4* bwarp = bfr + (size_t)wn * 128 + lane;   // + kt*1024 + nt*32
    constexpr int KTN = K / 16;

    uint2 B0[4], B1[4];
#pragma unroll
    for (int nt = 0; nt < 4; nt++) {
        B0[nt] = __ldg(reinterpret_cast<const uint2*>(bwarp + nt * 32));
        B1[nt] = __ldg(reinterpret_cast<const uint2*>(bwarp + 1024 + nt * 32));
    }

#pragma unroll 1
    for (int kt = 0; kt < KTN; kt++) {
        uint2 Bn[4];
        if (kt + 2 < KTN) {
#pragma unroll
            for (int nt = 0; nt < 4; nt++)
                Bn[nt] = __ldg(reinterpret_cast<const uint2*>(bwarp + (size_t)(kt + 2) * 1024 + nt * 32));
        }
#pragma unroll
        for (int q = 0; q < 4; q++) {
            uint4 Ah = ah4[(q * 16 + kt) * 32 + lane];
#pragma unroll
            for (int nt = 0; nt < 4; nt++)
                mma16816(acc[q][nt], Ah, B0[nt].x, B0[nt].y);   // A * W_hi
        }
#pragma unroll
        for (int nt = 0; nt < 4; nt++) { B0[nt] = B1[nt]; B1[nt] = Bn[nt]; }
    }

    // stage NEXT layer's params (overlaps epilogue)
    for (int i = tid; i < 3 * NEXTN; i += 256)
        parN[i] = (i < NEXTN) ? nb[i] : (i < 2 * NEXTN ? ng[i - NEXTN] : nbe[i - 2 * NEXTN]);

    // P1: bias + per-row partial sums, packed f32x2
    const int nbase = wn * 32 + (lane & 3) * 2;
    uint64_t bb2[4];
#pragma unroll
    for (int nt = 0; nt < 4; nt++) {
        float2 b2 = *reinterpret_cast<const float2*>(parC + nbase + nt * 8);
        bb2[nt] = pk2(b2.x, b2.y);
    }

#pragma unroll
    for (int q = 0; q < 4; q++) {
        uint64_t s1a2 = 0ull, s2a2 = 0ull, s1b2 = 0ull, s2b2 = 0ull;   // {0.f,0.f}
#pragma unroll
        for (int nt = 0; nt < 4; nt++) {
            uint64_t y01 = add2(pk2(acc[q][nt][0], acc[q][nt][1]), bb2[nt]);
            uint64_t y23 = add2(pk2(acc[q][nt][2], acc[q][nt][3]), bb2[nt]);
            upk2(y01, acc[q][nt][0], acc[q][nt][1]);
            upk2(y23, acc[q][nt][2], acc[q][nt][3]);
            s1a2 = add2(s1a2, y01); s2a2 = fma2(y01, y01, s2a2);
            s1b2 = add2(s1b2, y23); s2b2 = fma2(y23, y23, s2b2);
        }
        float u, v;
        upk2(s1a2, u, v); float s1a = u + v;
        upk2(s2a2, u, v); float s2a = u + v;
        upk2(s1b2, u, v); float s1b = u + v;
        upk2(s2b2, u, v); float s2b = u + v;
        s1a += __shfl_xor_sync(~0u, s1a, 1); s1a += __shfl_xor_sync(~0u, s1a, 2);
        s2a += __shfl_xor_sync(~0u, s2a, 1); s2a += __shfl_xor_sync(~0u, s2a, 2);
        s1b += __shfl_xor_sync(~0u, s1b, 1); s1b += __shfl_xor_sync(~0u, s1b, 2);
        s2b += __shfl_xor_sync(~0u, s2b, 1); s2b += __shfl_xor_sync(~0u, s2b, 2);
        if ((lane & 3) == 0) {
            int m0 = q * 16 + (lane >> 2);
            red1[wn * 64 + m0]     = s1a; red2[wn * 64 + m0]     = s2a;
            red1[wn * 64 + m0 + 8] = s1b; red2[wn * 64 + m0 + 8] = s2b;
        }
    }
    __syncthreads();
    if (tid < 64) {
        float t1 = 0.f, t2 = 0.f;
#pragma unroll
        for (int w = 0; w < 8; w++) { t1 += red1[w * 64 + tid]; t2 += red2[w * 64 + tid]; }
        float mean = t1 * (1.f / 256.f);
        float var  = fmaf(-mean, mean, t2 * (1.f / 256.f));
        float rstd = rsqrtf(var + EPSV);
        red1[tid] = mean; red2[tid] = rstd;
    }
    __syncthreads();

    // P3: packed-f32x2 normalize + packed-h2 activation + uint4 A-frag stores
    uint64_t gg2[4], ee2[4];
#pragma unroll
    for (int nt = 0; nt < 4; nt++) {
        float2 g2 = *reinterpret_cast<const float2*>(parC + 256 + nbase + nt * 8);
        float2 e2 = *reinterpret_cast<const float2*>(parC + 512 + nbase + nt * 8);
        gg2[nt] = pk2(g2.x, g2.y);
        ee2[nt] = pk2(e2.x, e2.y);
    }
    const int aln = ((lane >> 2) << 2) + (lane & 3);
#pragma unroll
    for (int q = 0; q < 4; q++) {
        int mA = q * 16 + (lane >> 2);
        float meanA = red1[mA],     rstdA = red2[mA];
        float meanB = red1[mA + 8], rstdB = red2[mA + 8];
        uint64_t rA2 = pk2(rstdA, rstdA);
        uint64_t rB2 = pk2(rstdB, rstdB);
        float mrA = -meanA * rstdA, mrB = -meanB * rstdB;
        uint64_t mA2 = pk2(mrA, mrA);
        uint64_t mB2 = pk2(mrB, mrB);
#pragma unroll
        for (int jp = 0; jp < 2; jp++) {     // ktile pair: nt = 2jp, 2jp+1
            uint32_t hv[4];
#pragma unroll
            for (int h = 0; h < 2; h++) {
                int nt = jp * 2 + h;
                uint64_t t01 = fma2(pk2(acc[q][nt][0], acc[q][nt][1]), rA2, mA2);
                uint64_t t23 = fma2(pk2(acc[q][nt][2], acc[q][nt][3]), rB2, mB2);
                uint64_t r01 = fma2(t01, gg2[nt], ee2[nt]);
                uint64_t r23 = fma2(t23, gg2[nt], ee2[nt]);
                float f0, f1, f2, f3;
                upk2(r01, f0, f1);
                upk2(r23, f2, f3);
                uint32_t hp0 = pack_f16(f0, f1);
                uint32_t hp1 = pack_f16(f2, f3);
                if (ACT) { hp0 = elu_h2(hp0); hp1 = elu_h2(hp1); }
                hv[h * 2]     = hp0;     // rows mA
                hv[h * 2 + 1] = hp1;     // rows mA+8
            }
            int idxb = ((q * 16 + wn * 2 + jp) * 32 + aln) * 4;
            *reinterpret_cast<uint4*>(ah + idxb) = make_uint4(hv[0], hv[1], hv[2], hv[3]);
        }
    }
    __syncthreads();
}

// final layer: K=256, N=32, 64 rows. Split-K across warp halves. (no ELU)
__device__ __forceinline__ void final_layer(
    unsigned char* smem, const uint4* __restrict__ bfr,
    const float* parC, float* __restrict__ out, int r0, int p, int tid)
{
    const int lane = tid & 31, wid = tid >> 5;
    const int m = wid & 3, kh = wid >> 2;
    const uint4* ah4 = reinterpret_cast<const uint4*>(smem + AFRAG_HI);
    float* scr = reinterpret_cast<float*>(smem);       // reused after barrier

    float acc[4][4];
#pragma unroll
    for (int nt = 0; nt < 4; nt++)
#pragma unroll
        for (int r = 0; r < 4; r++) acc[nt][r] = 0.f;

#pragma unroll 1
    for (int k = 0; k < 8; k++) {
        const int kt = kh * 8 + k;
        uint2 B[4];
#pragma unroll
        for (int nt = 0; nt < 4; nt++)
            B[nt] = __ldg(reinterpret_cast<const uint2*>(&bfr[((size_t)kt * 4 + nt) * 32 + lane]));
        uint4 Ah = ah4[(m * 16 + kt) * 32 + lane];
#pragma unroll
        for (int nt = 0; nt < 4; nt++)
            mma16816(acc[nt], Ah, B[nt].x, B[nt].y);
    }
    __syncthreads();     // all A-frag reads done; smem reusable
    if (kh == 1) {
        float4* s4 = reinterpret_cast<float4*>(scr) + (m * 32 + lane) * 4;
#pragma unroll
        for (int nt = 0; nt < 4; nt++)
            s4[nt] = make_float4(acc[nt][0], acc[nt][1], acc[nt][2], acc[nt][3]);
    }
    __syncthreads();
    if (kh == 1) return;

    const float4* s4 = reinterpret_cast<const float4*>(scr) + (m * 32 + lane) * 4;
#pragma unroll
    for (int nt = 0; nt < 4; nt++) {
        float4 v = s4[nt];
        acc[nt][0] += v.x; acc[nt][1] += v.y; acc[nt][2] += v.z; acc[nt][3] += v.w;
    }

    // bias + stats (warp-local: warp covers all 32 cols)
    const int nbase = (lane & 3) * 2;
    float s1a = 0.f, s2a = 0.f, s1b = 0.f, s2b = 0.f;
#pragma unroll
    for (int nt = 0; nt < 4; nt++) {
        float2 b2 = *reinterpret_cast<const float2*>(parC + nbase + nt * 8);
        float y0 = acc[nt][0] + b2.x, y1 = acc[nt][1] + b2.y;
        float y2 = acc[nt][2] + b2.x, y3 = acc[nt][3] + b2.y;
        acc[nt][0] = y0; acc[nt][1] = y1; acc[nt][2] = y2; acc[nt][3] = y3;
        s1a += y0 + y1; s2a = fmaf(y0, y0, fmaf(y1, y1, s2a));
        s1b += y2 + y3; s2b = fmaf(y2, y2, fmaf(y3, y3, s2b));
    }
    s1a += __shfl_xor_sync(~0u, s1a, 1); s1a += __shfl_xor_sync(~0u, s1a, 2);
    s2a += __shfl_xor_sync(~0u, s2a, 1); s2a += __shfl_xor_sync(~0u, s2a, 2);
    s1b += __shfl_xor_sync(~0u, s1b, 1); s1b += __shfl_xor_sync(~0u, s1b, 2);
    s2b += __shfl_xor_sync(~0u, s2b, 1); s2b += __shfl_xor_sync(~0u, s2b, 2);
    const float meanA = s1a * (1.f / 32.f);
    const float rstdA = rsqrtf(fmaf(-meanA, meanA, s2a * (1.f / 32.f)) + EPSV);
    const float meanB = s1b * (1.f / 32.f);
    const float rstdB = rsqrtf(fmaf(-meanB, meanB, s2b * (1.f / 32.f)) + EPSV);

    const int mA = m * 16 + (lane >> 2);
#pragma unroll
    for (int nt = 0; nt < 4; nt++) {
        int n0 = nbase + nt * 8;
        float2 g2 = *reinterpret_cast<const float2*>(parC + 32 + n0);
        float2 e2 = *reinterpret_cast<const float2*>(parC + 64 + n0);
        float2 o;
        o.x = fmaf((acc[nt][0] - meanA) * rstdA, g2.x, e2.x);
        o.y = fmaf((acc[nt][1] - meanA) * rstdA, g2.y, e2.y);
        *reinterpret_cast<float2*>(out + (size_t)(r0 + mA) * (NP * ACTD) + p * ACTD + n0) = o;
        o.x = fmaf((acc[nt][2] - meanB) * rstdB, g2.x, e2.x);
        o.y = fmaf((acc[nt][3] - meanB) * rstdB, g2.y, e2.y);
        *reinterpret_cast<float2*>(out + (size_t)(r0 + mA + 8) * (NP * ACTD) + p * ACTD + n0) = o;
    }
}

__global__ __launch_bounds__(256, 2)
void mlp_fused_kernel(
    const float* __restrict__ obs,
    const float* __restrict__ b1, const float* __restrict__ g1, const float* __restrict__ be1,
    const float* __restrict__ b2, const float* __restrict__ g2, const float* __restrict__ be2,
    const float* __restrict__ b3, const float* __restrict__ g3, const float* __restrict__ be3,
    const float* __restrict__ b4, const float* __restrict__ g4, const float* __restrict__ be4,
    float* __restrict__ out)
{
    extern __shared__ unsigned char smem[];
    const int tid = threadIdx.x;
    const int p   = blockIdx.y;
    const int r0  = blockIdx.x * MT;
    uint32_t* ah = reinterpret_cast<uint32_t*>(smem + AFRAG_HI);
    float* par0 = reinterpret_cast<float*>(smem + PAR0_OFF);
    float* par1 = reinterpret_cast<float*>(smem + PAR1_OFF);

    // stage obs A-frag image (linear copy; smem uint4 idx = img idx + mtile*256)
    {
        const uint4* src = reinterpret_cast<const uint4*>(g_obsimg) + (size_t)blockIdx.x * 1024;
        uint4* dst = reinterpret_cast<uint4*>(ah);
#pragma unroll
        for (int it = 0; it < 4; it++) {
            int i = tid + it * 256;
            dst[i + (i >> 8) * 256] = __ldg(src + i);
        }
        const float* s1 = b1 + p * HIDD;
        const float* s2 = g1 + p * HIDD;
        const float* s3 = be1 + p * HIDD;
        for (int i = tid; i < 768; i += 256)
            par0[i] = (i < 256) ? s1[i] : (i < 512 ? s2[i - 256] : s3[i - 512]);
    }
    __syncthreads();

    hidden_layer<OBSD, true, HIDD>(smem,
        reinterpret_cast<const uint4*>(g_wimg + OFF_L1 + (size_t)p * L1_BYTES),
        b2 + p * HIDD, g2 + p * HIDD, be2 + p * HIDD, par0, par1, tid);
    hidden_layer<HIDD, true, HIDD>(smem,
        reinterpret_cast<const uint4*>(g_wimg + OFF_L2 + (size_t)p * L2_BYTES),
        b3 + p * HIDD, g3 + p * HIDD, be3 + p * HIDD, par1, par0, tid);
    hidden_layer<HIDD, true, ACTD>(smem,
        reinterpret_cast<const uint4*>(g_wimg + OFF_L3 + (size_t)p * L2_BYTES),
        b4 + p * ACTD, g4 + p * ACTD, be4 + p * ACTD, par0, par1, tid);
    final_layer(smem,
        reinterpret_cast<const uint4*>(g_wimg + OFF_L4 + (size_t)p * L4_BYTES),
        par1, out, r0, p, tid);
}

// ---------------- launch ----------------
extern "C" void kernel_launch(void* const* d_in, const int* in_sizes, int n_in,
                              void* d_out, int out_size)
{
    const float* obs = (const float*)d_in[0];
    const float* W1  = (const float*)d_in[1];
    const float* b1  = (const float*)d_in[2];
    const float* g1  = (const float*)d_in[3];
    const float* be1 = (const float*)d_in[4];
    const float* W2  = (const float*)d_in[5];
    const float* b2  = (const float*)d_in[6];
    const float* g2  = (const float*)d_in[7];
    const float* be2 = (const float*)d_in[8];
    const float* W3  = (const float*)d_in[9];
    const float* b3  = (const float*)d_in[10];
    const float* g3  = (const float*)d_in[11];
    const float* be3 = (const float*)d_in[12];
    const float* W4  = (const float*)d_in[13];
    const float* b4  = (const float*)d_in[14];
    const float* g4  = (const float*)d_in[15];
    const float* be4 = (const float*)d_in[16];
    float* out = (float*)d_out;

    prep_all_kernel<<<dim3(NP, HIDD / 16, 5), 256>>>(W1, W2, W3, W4, obs);

    cudaFuncSetAttribute(mlp_fused_kernel,
                         cudaFuncAttributeMaxDynamicSharedMemorySize, DSMEM_BYTES);
    dim3 grid(NB / MT, NP);
    mlp_fused_kernel<<<grid, 256, DSMEM_BYTES>>>(
        obs, b1, g1, be1, b2, g2, be2, b3, g3, be3, b4, g4, be4, out);
}